// round 13
// baseline (speedup 1.0000x reference)
#include <cuda_runtime.h>
#include <cuda_fp16.h>
#include <cstdint>
#include <math.h>

#define B_TOTAL 65536
#define KDIM 512

// Packed fp16 limb layout.
// A (per m_blk of 128 rows): word idx = ((((m_blk*16+kc)*2+k16)*8+mt)*32+lane)*4 + r
//   lane: g=lane>>2, tig=lane&3.  reg r: row = mt*16+g+8*(r&1), k = kc*32+k16*16+tig*2+8*(r>>1), halves k,k+1
// B (per n_blk of 128 cols): word idx = ((((n_blk*16+kc)*2+k16)*8+np)*32+lane)*4 + r
//   r0 = b0 of group u=np*2 (n=np*16+g, k=tig*2), r1 = b1 (k+8), r2/r3 same for group u+1 (n+8)
#define A_BLK_U4 8192              // uint4 per m_blk per limb (32768 words)
#define W_NBLK_U4 8192             // uint4 per n_blk per limb
#define NSTAGE 3
#define STAGE_WORDS 8192                         // 32 KB per stage
#define SMEM_BYTES (NSTAGE * STAGE_WORDS * 4)    // 96 KB

// Scratch (allocation-free): A limb ping-pong + packed weights (21 n_blks)
__device__ uint4 g_A0a[4194304];
__device__ uint4 g_A1a[4194304];
__device__ uint4 g_A0b[4194304];
__device__ uint4 g_A1b[4194304];
__device__ uint4 g_W0[21 * W_NBLK_U4];
__device__ uint4 g_W1[21 * W_NBLK_U4];

__device__ __forceinline__ float act_clip(float h, int f, float mx) {
    float o;
    if (f == 0) {
        o = fmaxf(h, 0.0f);                       // ReLU
    } else if (f == 1) {
        o = 1.0f / (1.0f + __expf(-h));           // Sigmoid
    } else if (f == 2) {
        o = tanhf(h);                             // Tanh
    } else if (f == 3) {
        o = (h > 0.0f) ? h : 0.1f * h;            // LeakyReLU(0.1)
    } else {
        const float sc = 1.0507009873554805f;     // SELU
        const float al = 1.6732632423543772f;
        o = (h > 0.0f) ? sc * h : sc * al * (__expf(h) - 1.0f);
    }
    return fminf(o, mx);
}

// fp16 two-limb split of a float pair -> (h0 word, h1 word), low half = first element
__device__ __forceinline__ void split2(float x, float y, uint32_t& w0, uint32_t& w1) {
    const __half hx = __float2half_rn(x);
    const __half hy = __float2half_rn(y);
    const __half lx = __float2half_rn(x - __half2float(hx));
    const __half ly = __float2half_rn(y - __half2float(hy));
    w0 = (uint32_t)__half_as_ushort(hx) | ((uint32_t)__half_as_ushort(hy) << 16);
    w1 = (uint32_t)__half_as_ushort(lx) | ((uint32_t)__half_as_ushort(ly) << 16);
}

// fp32-accumulating fp16 mma (main hi*hi term)
__device__ __forceinline__ void mma16(float* d, const uint4& a, uint32_t b0, uint32_t b1) {
    asm volatile(
        "mma.sync.aligned.m16n8k16.row.col.f32.f16.f16.f32 "
        "{%0,%1,%2,%3}, {%4,%5,%6,%7}, {%8,%9}, {%0,%1,%2,%3};"
        : "+f"(d[0]), "+f"(d[1]), "+f"(d[2]), "+f"(d[3])
        : "r"(a.x), "r"(a.y), "r"(a.z), "r"(a.w), "r"(b0), "r"(b1));
}

// fp16-accumulating fp16 mma (cross terms; D = 2 x f16x2 regs)
__device__ __forceinline__ void mma16h(uint32_t* d, const uint4& a, uint32_t b0, uint32_t b1) {
    asm volatile(
        "mma.sync.aligned.m16n8k16.row.col.f16.f16.f16.f16 "
        "{%0,%1}, {%2,%3,%4,%5}, {%6,%7}, {%0,%1};"
        : "+r"(d[0]), "+r"(d[1])
        : "r"(a.x), "r"(a.y), "r"(a.z), "r"(a.w), "r"(b0), "r"(b1));
}

__device__ __forceinline__ void cp_async16(uint32_t dst, const void* src) {
    asm volatile("cp.async.cg.shared.global [%0], [%1], 16;" :: "r"(dst), "l"(src));
}

// ---- pack: fp32 row-major [rows, 512] -> fp16 limb fragment layout ----
// One thread per uint4 granule (each consumes 8 floats).
__global__ void __launch_bounds__(256)
pack_a16(const float* __restrict__ src, uint4* __restrict__ d0, uint4* __restrict__ d1)
{
    const uint32_t gid = blockIdx.x * 256 + threadIdx.x;   // 4,194,304 total
    const int lane = gid & 31;
    const int mt   = (gid >> 5) & 7;
    const int k16  = (gid >> 8) & 1;
    const int kc   = (gid >> 9) & 15;
    const int mblk = gid >> 13;
    const int g = lane >> 2, tig = lane & 3;
    const int row0 = mblk * 128 + mt * 16 + g;
    const int k0 = kc * 32 + k16 * 16 + tig * 2;
    const float2 p00 = *(const float2*)(src + (size_t)row0 * KDIM + k0);
    const float2 p10 = *(const float2*)(src + (size_t)(row0 + 8) * KDIM + k0);
    const float2 p01 = *(const float2*)(src + (size_t)row0 * KDIM + k0 + 8);
    const float2 p11 = *(const float2*)(src + (size_t)(row0 + 8) * KDIM + k0 + 8);
    uint4 h, l;
    split2(p00.x, p00.y, h.x, l.x);   // a0: (row g,   k..k+1)
    split2(p10.x, p10.y, h.y, l.y);   // a1: (row g+8, k..k+1)
    split2(p01.x, p01.y, h.z, l.z);   // a2: (row g,   k+8..k+9)
    split2(p11.x, p11.y, h.w, l.w);   // a3: (row g+8, k+8..k+9)
    d0[gid] = h;
    d1[gid] = l;
}

__global__ void __launch_bounds__(256)
pack_w16(const float* __restrict__ src, uint4* __restrict__ d0, uint4* __restrict__ d1)
{
    const uint32_t gid = blockIdx.x * 256 + threadIdx.x;
    const int lane = gid & 31;
    const int np   = (gid >> 5) & 7;
    const int k16  = (gid >> 8) & 1;
    const int kc   = (gid >> 9) & 15;
    const int nblk = gid >> 13;
    const int g = lane >> 2, tig = lane & 3;
    const int n0 = nblk * 128 + np * 16 + g;     // group u = np*2
    const int k0 = kc * 32 + k16 * 16 + tig * 2;
    const float2 q00 = *(const float2*)(src + (size_t)n0 * KDIM + k0);
    const float2 q01 = *(const float2*)(src + (size_t)n0 * KDIM + k0 + 8);
    const float2 q10 = *(const float2*)(src + (size_t)(n0 + 8) * KDIM + k0);
    const float2 q11 = *(const float2*)(src + (size_t)(n0 + 8) * KDIM + k0 + 8);
    uint4 h, l;
    split2(q00.x, q00.y, h.x, l.x);   // b0 of group u
    split2(q01.x, q01.y, h.y, l.y);   // b1 of group u
    split2(q10.x, q10.y, h.z, l.z);   // b0 of group u+1
    split2(q11.x, q11.y, h.w, l.w);   // b1 of group u+1
    d0[gid] = h;
    d1[gid] = l;
}

// ---- fused fp16x2-limb GEMM layer: act_clip(A @ W^T + bias) ----
// CTA 128x128 tile, BK=32, 3-stage cp.async pipeline (1 sync/chunk), 8 warps.
// hi*hi in fp32 accum; both cross terms chained into one fp16 accumulator.
__global__ void __launch_bounds__(256)
fused_layer16(const uint4* __restrict__ A0, const uint4* __restrict__ A1,
              const uint4* __restrict__ B0, const uint4* __restrict__ B1,
              const float* __restrict__ bias,
              const int*   __restrict__ fid,
              const float* __restrict__ mx,
              uint32_t* __restrict__ C0, uint32_t* __restrict__ C1,
              float* __restrict__ Cout,
              int Nout, int split_out)
{
    extern __shared__ __align__(16) uint32_t smw[];

    const int tid = threadIdx.x;
    const int w   = tid >> 5;
    const int l   = tid & 31;
    const int bn  = blockIdx.x * 128;
    const int wm  = w & 3;            // m block (rows wm*32)
    const int wn  = w >> 2;           // n half (cols wn*64)

    const uint32_t smem_addr = (uint32_t)__cvta_generic_to_shared(smw);
    const size_t a_base = (size_t)blockIdx.y * A_BLK_U4;
    const size_t b_base = (size_t)blockIdx.x * W_NBLK_U4;

    float acc[2][8][4];
    uint32_t accx[2][8][2];
    #pragma unroll
    for (int i = 0; i < 2; ++i)
        #pragma unroll
        for (int u = 0; u < 8; ++u) {
            #pragma unroll
            for (int r = 0; r < 4; ++r) acc[i][u][r] = 0.0f;
            accx[i][u][0] = 0u;
            accx[i][u][1] = 0u;
        }

    #define ISSUE_CHUNK(kc_) do {                                             \
        const uint32_t dstb = smem_addr + ((kc_) % NSTAGE) * (STAGE_WORDS*4); \
        const uint4* pA0 = A0 + a_base + (size_t)(kc_) * 512;                 \
        const uint4* pA1 = A1 + a_base + (size_t)(kc_) * 512;                 \
        const uint4* pB0 = B0 + b_base + (size_t)(kc_) * 512;                 \
        const uint4* pB1 = B1 + b_base + (size_t)(kc_) * 512;                 \
        _Pragma("unroll")                                                     \
        for (int j = 0; j < 2; ++j) {                                         \
            const int g16 = tid + j * 256;                                    \
            cp_async16(dstb +         g16 * 16, pA0 + g16);                   \
            cp_async16(dstb +  8192 + g16 * 16, pA1 + g16);                   \
            cp_async16(dstb + 16384 + g16 * 16, pB0 + g16);                   \
            cp_async16(dstb + 24576 + g16 * 16, pB1 + g16);                   \
        }                                                                     \
        asm volatile("cp.async.commit_group;" ::: "memory");                  \
    } while (0)

    // Prologue: 2 chunks in flight.
    ISSUE_CHUNK(0);
    ISSUE_CHUNK(1);

    constexpr int NCHUNK = KDIM / 32;   // 16
    for (int kc = 0; kc < NCHUNK; ++kc) {
        asm volatile("cp.async.wait_group 1;" ::: "memory");
        __syncthreads();

        // Refill the slot consumed at kc-1 (all reads ordered by the sync above).
        if (kc + 2 < NCHUNK) ISSUE_CHUNK(kc + 2);

        const uint32_t* sw = smw + (kc % NSTAGE) * STAGE_WORDS;
        #pragma unroll
        for (int k16 = 0; k16 < 2; ++k16) {
            const uint32_t* awb = sw + k16 * 1024;
            const uint4 ah0 = *(const uint4*)(awb + (wm * 2 + 0) * 128 + l * 4);
            const uint4 ah1 = *(const uint4*)(awb + (wm * 2 + 1) * 128 + l * 4);
            const uint4 al0 = *(const uint4*)(awb + 2048 + (wm * 2 + 0) * 128 + l * 4);
            const uint4 al1 = *(const uint4*)(awb + 2048 + (wm * 2 + 1) * 128 + l * 4);
            const uint32_t* bwb = sw + 4096 + k16 * 1024;
            #pragma unroll
            for (int pp = 0; pp < 4; ++pp) {
                const int np = wn * 4 + pp;
                const uint4 bh = *(const uint4*)(bwb + np * 128 + l * 4);
                const uint4 bl = *(const uint4*)(bwb + 2048 + np * 128 + l * 4);
                // group u = pp*2 (regs .x,.y), group u+1 (regs .z,.w)
                // fp32: h0a*h0b.  fp16 chain: h0a*h1b + h1a*h0b.
                mma16 (acc[0][pp * 2],      ah0, bh.x, bh.y);
                mma16h(accx[0][pp * 2],     ah0, bl.x, bl.y);
                mma16h(accx[0][pp * 2],     al0, bh.x, bh.y);
                mma16 (acc[1][pp * 2],      ah1, bh.x, bh.y);
                mma16h(accx[1][pp * 2],     ah1, bl.x, bl.y);
                mma16h(accx[1][pp * 2],     al1, bh.x, bh.y);
                mma16 (acc[0][pp * 2 + 1],  ah0, bh.z, bh.w);
                mma16h(accx[0][pp * 2 + 1], ah0, bl.z, bl.w);
                mma16h(accx[0][pp * 2 + 1], al0, bh.z, bh.w);
                mma16 (acc[1][pp * 2 + 1],  ah1, bh.z, bh.w);
                mma16h(accx[1][pp * 2 + 1], ah1, bl.z, bl.w);
                mma16h(accx[1][pp * 2 + 1], al1, bh.z, bh.w);
            }
        }
    }

    // ---- epilogue ----
    const int g = l >> 2;
    #pragma unroll
    for (int u = 0; u < 8; ++u) {
        const int col = bn + wn * 64 + u * 8 + (l & 3) * 2;
        const float bv0 = __ldg(bias + col);
        const float bv1 = __ldg(bias + col + 1);
        const int   f0  = __ldg(fid + col);
        const int   f1  = __ldg(fid + col + 1);
        const float m0  = __ldg(mx + col);
        const float m1  = __ldg(mx + col + 1);
        #pragma unroll
        for (int i = 0; i < 2; ++i) {
            const float* a4 = acc[i][u];
            // f16 accum layout: reg0 = {(g,col), (g,col+1)}, reg1 = {(g+8,col), (g+8,col+1)}
            const float2 x0 = __half22float2(*reinterpret_cast<const __half2*>(&accx[i][u][0]));
            const float2 x1 = __half22float2(*reinterpret_cast<const __half2*>(&accx[i][u][1]));
            const float v00 = act_clip(a4[0] + x0.x + bv0, f0, m0);  // (row g,   col)
            const float v01 = act_clip(a4[1] + x0.y + bv1, f1, m1);  // (row g,   col+1)
            const float v10 = act_clip(a4[2] + x1.x + bv0, f0, m0);  // (row g+8, col)
            const float v11 = act_clip(a4[3] + x1.y + bv1, f1, m1);  // (row g+8, col+1)
            if (split_out) {
                // packed fp16-limb write for next layer's A
                const int kc_  = col >> 5;
                const int k16_ = (col >> 4) & 1;
                const int kb   = (col >> 3) & 1;
                const int mt_  = wm * 2 + i;
                const size_t wb =
                    ((((size_t)blockIdx.y * 16 + kc_) * 2 + k16_) * 8 + mt_) * 128
                    + (size_t)l * 4;
                uint32_t w0h, w0l, w1h, w1l;
                split2(v00, v01, w0h, w0l);
                split2(v10, v11, w1h, w1l);
                C0[wb + 2 * kb]     = w0h;  C1[wb + 2 * kb]     = w0l;
                C0[wb + 1 + 2 * kb] = w1h;  C1[wb + 1 + 2 * kb] = w1l;
            } else {
                const int row0 = blockIdx.y * 128 + wm * 32 + i * 16 + g;
                *(float2*)(Cout + (size_t)row0 * Nout + col)       = make_float2(v00, v01);
                *(float2*)(Cout + (size_t)(row0 + 8) * Nout + col) = make_float2(v10, v11);
            }
        }
    }
}

extern "C" void kernel_launch(void* const* d_in, const int* in_sizes, int n_in,
                              void* d_out, int out_size) {
    const float* x      = (const float*)d_in[0];   // [65536, 512]
    const float* W_in   = (const float*)d_in[1];   // [512, 512]
    const float* b_in   = (const float*)d_in[2];   // [512]
    const float* W_h    = (const float*)d_in[3];   // [4, 512, 512]
    const float* b_h    = (const float*)d_in[4];   // [4, 512]
    const float* W_out  = (const float*)d_in[5];   // [128, 512]
    const float* b_out  = (const float*)d_in[6];   // [128]
    const float* m_in   = (const float*)d_in[7];   // [512]
    const float* m_h    = (const float*)d_in[8];   // [4, 512]
    const float* m_out  = (const float*)d_in[9];   // [128]
    const int*   fid_in = (const int*)d_in[10];    // [512]
    const int*   fid_h  = (const int*)d_in[11];    // [4, 512]
    const int*   fid_out= (const int*)d_in[12];    // [128]
    float* out = (float*)d_out;                    // [65536, 128]

    uint4 *A0a, *A1a, *A0b, *A1b, *W0, *W1;
    cudaGetSymbolAddress((void**)&A0a, g_A0a);
    cudaGetSymbolAddress((void**)&A1a, g_A1a);
    cudaGetSymbolAddress((void**)&A0b, g_A0b);
    cudaGetSymbolAddress((void**)&A1b, g_A1b);
    cudaGetSymbolAddress((void**)&W0, g_W0);
    cudaGetSymbolAddress((void**)&W1, g_W1);

    cudaFuncSetAttribute(fused_layer16,
                         cudaFuncAttributeMaxDynamicSharedMemorySize, SMEM_BYTES);

    // ---- one-time packing into fp16 limb fragment layout ----
    pack_a16<<<16384, 256>>>(x, A0a, A1a);
    pack_w16<<<128, 256>>>(W_in,  W0,                W1);                   // 4 n_blks
    pack_w16<<<512, 256>>>(W_h,   W0 + 4 * W_NBLK_U4,  W1 + 4 * W_NBLK_U4); // 16 n_blks
    pack_w16<<<32, 256>>>(W_out,  W0 + 20 * W_NBLK_U4, W1 + 20 * W_NBLK_U4);// 1 n_blk

    dim3 blk(256);
    dim3 g512(4, B_TOTAL / 128);
    dim3 g128(1, B_TOTAL / 128);

    // input layer: packed A(a) -> packed A(b)
    fused_layer16<<<g512, blk, SMEM_BYTES>>>(A0a, A1a, W0, W1,
                                             b_in, fid_in, m_in,
                                             (uint32_t*)A0b, (uint32_t*)A1b,
                                             nullptr, 512, 1);

    // 4 hidden layers, ping-pong
    const uint4* c0 = A0b; const uint4* c1 = A1b;
    uint4* n0 = A0a;       uint4* n1 = A1a;
    for (int i = 0; i < 4; ++i) {
        const size_t woff = (size_t)(4 + 4 * i) * W_NBLK_U4;
        fused_layer16<<<g512, blk, SMEM_BYTES>>>(c0, c1, W0 + woff, W1 + woff,
                                                 b_h + i * 512,
                                                 fid_h + i * 512,
                                                 m_h + i * 512,
                                                 (uint32_t*)n0, (uint32_t*)n1,
                                                 nullptr, 512, 1);
        uint4* t0 = n0; uint4* t1 = n1;
        n0 = (uint4*)c0; n1 = (uint4*)c1;
        c0 = t0; c1 = t1;
    }

    // output layer: plain fp32 row-major out
    fused_layer16<<<g128, blk, SMEM_BYTES>>>(c0, c1,
                                             W0 + 20 * W_NBLK_U4, W1 + 20 * W_NBLK_U4,
                                             b_out, fid_out, m_out,
                                             nullptr, nullptr, out, 128, 0);
}

// round 14
// speedup vs baseline: 1.6289x; 1.6289x over previous
#include <cuda_runtime.h>
#include <cuda_fp16.h>
#include <cstdint>
#include <math.h>

#define B_TOTAL 65536
#define KDIM 512

// Packed fp16 limb layout.
// A (per m_blk of 128 rows): word idx = ((((m_blk*16+kc)*2+k16)*8+mt)*32+lane)*4 + r
//   lane: g=lane>>2, tig=lane&3.  reg r: row = mt*16+g+8*(r&1), k = kc*32+k16*16+tig*2+8*(r>>1), halves k,k+1
// B (per n_blk of 128 cols): word idx = ((((n_blk*16+kc)*2+k16)*8+np)*32+lane)*4 + r
//   r0 = b0 of group u=np*2 (n=np*16+g, k=tig*2), r1 = b1 (k+8), r2/r3 same for group u+1 (n+8)
#define A_BLK_U4 8192              // uint4 per m_blk per limb (32768 words)
#define W_NBLK_U4 8192             // uint4 per n_blk per limb
#define NSTAGE 3
#define STAGE_WORDS 8192                         // 32 KB per stage
#define SMEM_BYTES (NSTAGE * STAGE_WORDS * 4)    // 96 KB

// Scratch (allocation-free): A limb ping-pong + packed weights (21 n_blks)
__device__ uint4 g_A0a[4194304];
__device__ uint4 g_A1a[4194304];
__device__ uint4 g_A0b[4194304];
__device__ uint4 g_A1b[4194304];
__device__ uint4 g_W0[21 * W_NBLK_U4];
__device__ uint4 g_W1[21 * W_NBLK_U4];

__device__ __forceinline__ float act_clip(float h, int f, float mx) {
    float o;
    if (f == 0) {
        o = fmaxf(h, 0.0f);                       // ReLU
    } else if (f == 1) {
        o = 1.0f / (1.0f + __expf(-h));           // Sigmoid
    } else if (f == 2) {
        o = tanhf(h);                             // Tanh
    } else if (f == 3) {
        o = (h > 0.0f) ? h : 0.1f * h;            // LeakyReLU(0.1)
    } else {
        const float sc = 1.0507009873554805f;     // SELU
        const float al = 1.6732632423543772f;
        o = (h > 0.0f) ? sc * h : sc * al * (__expf(h) - 1.0f);
    }
    return fminf(o, mx);
}

// fp16 two-limb split of a float pair -> (h0 word, h1 word), low half = first element
__device__ __forceinline__ void split2(float x, float y, uint32_t& w0, uint32_t& w1) {
    const __half hx = __float2half_rn(x);
    const __half hy = __float2half_rn(y);
    const __half lx = __float2half_rn(x - __half2float(hx));
    const __half ly = __float2half_rn(y - __half2float(hy));
    w0 = (uint32_t)__half_as_ushort(hx) | ((uint32_t)__half_as_ushort(hy) << 16);
    w1 = (uint32_t)__half_as_ushort(lx) | ((uint32_t)__half_as_ushort(ly) << 16);
}

// fp32-accumulating fp16 mma. NOT volatile: outputs keep it alive, and the
// scheduler is free to interleave independent chains.
__device__ __forceinline__ void mma16(float* d, const uint4& a, uint32_t b0, uint32_t b1) {
    asm("mma.sync.aligned.m16n8k16.row.col.f32.f16.f16.f32 "
        "{%0,%1,%2,%3}, {%4,%5,%6,%7}, {%8,%9}, {%0,%1,%2,%3};"
        : "+f"(d[0]), "+f"(d[1]), "+f"(d[2]), "+f"(d[3])
        : "r"(a.x), "r"(a.y), "r"(a.z), "r"(a.w), "r"(b0), "r"(b1));
}

__device__ __forceinline__ void cp_async16(uint32_t dst, const void* src) {
    asm volatile("cp.async.cg.shared.global [%0], [%1], 16;" :: "r"(dst), "l"(src));
}

// ---- pack: fp32 row-major [rows, 512] -> fp16 limb fragment layout ----
// One thread per uint4 granule (each consumes 8 floats).
__global__ void __launch_bounds__(256)
pack_a16(const float* __restrict__ src, uint4* __restrict__ d0, uint4* __restrict__ d1)
{
    const uint32_t gid = blockIdx.x * 256 + threadIdx.x;   // 4,194,304 total
    const int lane = gid & 31;
    const int mt   = (gid >> 5) & 7;
    const int k16  = (gid >> 8) & 1;
    const int kc   = (gid >> 9) & 15;
    const int mblk = gid >> 13;
    const int g = lane >> 2, tig = lane & 3;
    const int row0 = mblk * 128 + mt * 16 + g;
    const int k0 = kc * 32 + k16 * 16 + tig * 2;
    const float2 p00 = *(const float2*)(src + (size_t)row0 * KDIM + k0);
    const float2 p10 = *(const float2*)(src + (size_t)(row0 + 8) * KDIM + k0);
    const float2 p01 = *(const float2*)(src + (size_t)row0 * KDIM + k0 + 8);
    const float2 p11 = *(const float2*)(src + (size_t)(row0 + 8) * KDIM + k0 + 8);
    uint4 h, l;
    split2(p00.x, p00.y, h.x, l.x);   // a0: (row g,   k..k+1)
    split2(p10.x, p10.y, h.y, l.y);   // a1: (row g+8, k..k+1)
    split2(p01.x, p01.y, h.z, l.z);   // a2: (row g,   k+8..k+9)
    split2(p11.x, p11.y, h.w, l.w);   // a3: (row g+8, k+8..k+9)
    d0[gid] = h;
    d1[gid] = l;
}

__global__ void __launch_bounds__(256)
pack_w16(const float* __restrict__ src, uint4* __restrict__ d0, uint4* __restrict__ d1)
{
    const uint32_t gid = blockIdx.x * 256 + threadIdx.x;
    const int lane = gid & 31;
    const int np   = (gid >> 5) & 7;
    const int k16  = (gid >> 8) & 1;
    const int kc   = (gid >> 9) & 15;
    const int nblk = gid >> 13;
    const int g = lane >> 2, tig = lane & 3;
    const int n0 = nblk * 128 + np * 16 + g;     // group u = np*2
    const int k0 = kc * 32 + k16 * 16 + tig * 2;
    const float2 q00 = *(const float2*)(src + (size_t)n0 * KDIM + k0);
    const float2 q01 = *(const float2*)(src + (size_t)n0 * KDIM + k0 + 8);
    const float2 q10 = *(const float2*)(src + (size_t)(n0 + 8) * KDIM + k0);
    const float2 q11 = *(const float2*)(src + (size_t)(n0 + 8) * KDIM + k0 + 8);
    uint4 h, l;
    split2(q00.x, q00.y, h.x, l.x);   // b0 of group u
    split2(q01.x, q01.y, h.y, l.y);   // b1 of group u
    split2(q10.x, q10.y, h.z, l.z);   // b0 of group u+1
    split2(q11.x, q11.y, h.w, l.w);   // b1 of group u+1
    d0[gid] = h;
    d1[gid] = l;
}

// ---- fused fp16x2-limb GEMM layer: act_clip(A @ W^T + bias) ----
// CTA 128x128 tile, BK=32, 3-stage cp.async pipeline (1 sync/chunk), 8 warps.
// Term-major mma order: all 16 hh, then 16 hl, then 16 lh per k16 — dependent
// mmas on the same accumulator are 16 issues apart (latency hidden).
__global__ void __launch_bounds__(256)
fused_layer16(const uint4* __restrict__ A0, const uint4* __restrict__ A1,
              const uint4* __restrict__ B0, const uint4* __restrict__ B1,
              const float* __restrict__ bias,
              const int*   __restrict__ fid,
              const float* __restrict__ mx,
              uint32_t* __restrict__ C0, uint32_t* __restrict__ C1,
              float* __restrict__ Cout,
              int Nout, int split_out)
{
    extern __shared__ __align__(16) uint32_t smw[];

    const int tid = threadIdx.x;
    const int w   = tid >> 5;
    const int l   = tid & 31;
    const int bn  = blockIdx.x * 128;
    const int wm  = w & 3;            // m block (rows wm*32)
    const int wn  = w >> 2;           // n half (cols wn*64)

    const uint32_t smem_addr = (uint32_t)__cvta_generic_to_shared(smw);
    const size_t a_base = (size_t)blockIdx.y * A_BLK_U4;
    const size_t b_base = (size_t)blockIdx.x * W_NBLK_U4;

    float acc[2][8][4];
    #pragma unroll
    for (int i = 0; i < 2; ++i)
        #pragma unroll
        for (int u = 0; u < 8; ++u)
            #pragma unroll
            for (int r = 0; r < 4; ++r) acc[i][u][r] = 0.0f;

    #define ISSUE_CHUNK(kc_) do {                                             \
        const uint32_t dstb = smem_addr + ((kc_) % NSTAGE) * (STAGE_WORDS*4); \
        const uint4* pA0 = A0 + a_base + (size_t)(kc_) * 512;                 \
        const uint4* pA1 = A1 + a_base + (size_t)(kc_) * 512;                 \
        const uint4* pB0 = B0 + b_base + (size_t)(kc_) * 512;                 \
        const uint4* pB1 = B1 + b_base + (size_t)(kc_) * 512;                 \
        _Pragma("unroll")                                                     \
        for (int j = 0; j < 2; ++j) {                                         \
            const int g16 = tid + j * 256;                                    \
            cp_async16(dstb +         g16 * 16, pA0 + g16);                   \
            cp_async16(dstb +  8192 + g16 * 16, pA1 + g16);                   \
            cp_async16(dstb + 16384 + g16 * 16, pB0 + g16);                   \
            cp_async16(dstb + 24576 + g16 * 16, pB1 + g16);                   \
        }                                                                     \
        asm volatile("cp.async.commit_group;" ::: "memory");                  \
    } while (0)

    // Prologue: 2 chunks in flight.
    ISSUE_CHUNK(0);
    ISSUE_CHUNK(1);

    constexpr int NCHUNK = KDIM / 32;   // 16
    for (int kc = 0; kc < NCHUNK; ++kc) {
        asm volatile("cp.async.wait_group 1;" ::: "memory");
        __syncthreads();

        // Refill the slot consumed at kc-1 (all reads ordered by the sync above).
        if (kc + 2 < NCHUNK) ISSUE_CHUNK(kc + 2);

        const uint32_t* sw = smw + (kc % NSTAGE) * STAGE_WORDS;
        #pragma unroll
        for (int k16 = 0; k16 < 2; ++k16) {
            const uint32_t* awb = sw + k16 * 1024;
            const uint4 ah0 = *(const uint4*)(awb + (wm * 2 + 0) * 128 + l * 4);
            const uint4 ah1 = *(const uint4*)(awb + (wm * 2 + 1) * 128 + l * 4);
            const uint4 al0 = *(const uint4*)(awb + 2048 + (wm * 2 + 0) * 128 + l * 4);
            const uint4 al1 = *(const uint4*)(awb + 2048 + (wm * 2 + 1) * 128 + l * 4);
            const uint32_t* bwb = sw + 4096 + k16 * 1024;
            uint4 bh[4], bl[4];
            #pragma unroll
            for (int pp = 0; pp < 4; ++pp) {
                const int np = wn * 4 + pp;
                bh[pp] = *(const uint4*)(bwb + np * 128 + l * 4);
                bl[pp] = *(const uint4*)(bwb + 2048 + np * 128 + l * 4);
            }
            // Term 1: hh — 16 independent accumulators
            #pragma unroll
            for (int pp = 0; pp < 4; ++pp) {
                mma16(acc[0][pp * 2],     ah0, bh[pp].x, bh[pp].y);
                mma16(acc[1][pp * 2],     ah1, bh[pp].x, bh[pp].y);
                mma16(acc[0][pp * 2 + 1], ah0, bh[pp].z, bh[pp].w);
                mma16(acc[1][pp * 2 + 1], ah1, bh[pp].z, bh[pp].w);
            }
            // Term 2: hl
            #pragma unroll
            for (int pp = 0; pp < 4; ++pp) {
                mma16(acc[0][pp * 2],     ah0, bl[pp].x, bl[pp].y);
                mma16(acc[1][pp * 2],     ah1, bl[pp].x, bl[pp].y);
                mma16(acc[0][pp * 2 + 1], ah0, bl[pp].z, bl[pp].w);
                mma16(acc[1][pp * 2 + 1], ah1, bl[pp].z, bl[pp].w);
            }
            // Term 3: lh
            #pragma unroll
            for (int pp = 0; pp < 4; ++pp) {
                mma16(acc[0][pp * 2],     al0, bh[pp].x, bh[pp].y);
                mma16(acc[1][pp * 2],     al1, bh[pp].x, bh[pp].y);
                mma16(acc[0][pp * 2 + 1], al0, bh[pp].z, bh[pp].w);
                mma16(acc[1][pp * 2 + 1], al1, bh[pp].z, bh[pp].w);
            }
        }
    }

    // ---- epilogue ----
    const int g = l >> 2;
    #pragma unroll
    for (int u = 0; u < 8; ++u) {
        const int col = bn + wn * 64 + u * 8 + (l & 3) * 2;
        const float bv0 = __ldg(bias + col);
        const float bv1 = __ldg(bias + col + 1);
        const int   f0  = __ldg(fid + col);
        const int   f1  = __ldg(fid + col + 1);
        const float m0  = __ldg(mx + col);
        const float m1  = __ldg(mx + col + 1);
        #pragma unroll
        for (int i = 0; i < 2; ++i) {
            const float* a4 = acc[i][u];
            const float v00 = act_clip(a4[0] + bv0, f0, m0);  // (row g,   col)
            const float v01 = act_clip(a4[1] + bv1, f1, m1);  // (row g,   col+1)
            const float v10 = act_clip(a4[2] + bv0, f0, m0);  // (row g+8, col)
            const float v11 = act_clip(a4[3] + bv1, f1, m1);  // (row g+8, col+1)
            if (split_out) {
                // packed fp16-limb write for next layer's A
                const int kc_  = col >> 5;
                const int k16_ = (col >> 4) & 1;
                const int kb   = (col >> 3) & 1;
                const int mt_  = wm * 2 + i;
                const size_t wb =
                    ((((size_t)blockIdx.y * 16 + kc_) * 2 + k16_) * 8 + mt_) * 128
                    + (size_t)l * 4;
                uint32_t w0h, w0l, w1h, w1l;
                split2(v00, v01, w0h, w0l);
                split2(v10, v11, w1h, w1l);
                C0[wb + 2 * kb]     = w0h;  C1[wb + 2 * kb]     = w0l;
                C0[wb + 1 + 2 * kb] = w1h;  C1[wb + 1 + 2 * kb] = w1l;
            } else {
                const int row0 = blockIdx.y * 128 + wm * 32 + i * 16 + g;
                *(float2*)(Cout + (size_t)row0 * Nout + col)       = make_float2(v00, v01);
                *(float2*)(Cout + (size_t)(row0 + 8) * Nout + col) = make_float2(v10, v11);
            }
        }
    }
}

extern "C" void kernel_launch(void* const* d_in, const int* in_sizes, int n_in,
                              void* d_out, int out_size) {
    const float* x      = (const float*)d_in[0];   // [65536, 512]
    const float* W_in   = (const float*)d_in[1];   // [512, 512]
    const float* b_in   = (const float*)d_in[2];   // [512]
    const float* W_h    = (const float*)d_in[3];   // [4, 512, 512]
    const float* b_h    = (const float*)d_in[4];   // [4, 512]
    const float* W_out  = (const float*)d_in[5];   // [128, 512]
    const float* b_out  = (const float*)d_in[6];   // [128]
    const float* m_in   = (const float*)d_in[7];   // [512]
    const float* m_h    = (const float*)d_in[8];   // [4, 512]
    const float* m_out  = (const float*)d_in[9];   // [128]
    const int*   fid_in = (const int*)d_in[10];    // [512]
    const int*   fid_h  = (const int*)d_in[11];    // [4, 512]
    const int*   fid_out= (const int*)d_in[12];    // [128]
    float* out = (float*)d_out;                    // [65536, 128]

    uint4 *A0a, *A1a, *A0b, *A1b, *W0, *W1;
    cudaGetSymbolAddress((void**)&A0a, g_A0a);
    cudaGetSymbolAddress((void**)&A1a, g_A1a);
    cudaGetSymbolAddress((void**)&A0b, g_A0b);
    cudaGetSymbolAddress((void**)&A1b, g_A1b);
    cudaGetSymbolAddress((void**)&W0, g_W0);
    cudaGetSymbolAddress((void**)&W1, g_W1);

    cudaFuncSetAttribute(fused_layer16,
                         cudaFuncAttributeMaxDynamicSharedMemorySize, SMEM_BYTES);

    // ---- one-time packing into fp16 limb fragment layout ----
    pack_a16<<<16384, 256>>>(x, A0a, A1a);
    pack_w16<<<128, 256>>>(W_in,  W0,                W1);                   // 4 n_blks
    pack_w16<<<512, 256>>>(W_h,   W0 + 4 * W_NBLK_U4,  W1 + 4 * W_NBLK_U4); // 16 n_blks
    pack_w16<<<32, 256>>>(W_out,  W0 + 20 * W_NBLK_U4, W1 + 20 * W_NBLK_U4);// 1 n_blk

    dim3 blk(256);
    dim3 g512(4, B_TOTAL / 128);
    dim3 g128(1, B_TOTAL / 128);

    // input layer: packed A(a) -> packed A(b)
    fused_layer16<<<g512, blk, SMEM_BYTES>>>(A0a, A1a, W0, W1,
                                             b_in, fid_in, m_in,
                                             (uint32_t*)A0b, (uint32_t*)A1b,
                                             nullptr, 512, 1);

    // 4 hidden layers, ping-pong
    const uint4* c0 = A0b; const uint4* c1 = A1b;
    uint4* n0 = A0a;       uint4* n1 = A1a;
    for (int i = 0; i < 4; ++i) {
        const size_t woff = (size_t)(4 + 4 * i) * W_NBLK_U4;
        fused_layer16<<<g512, blk, SMEM_BYTES>>>(c0, c1, W0 + woff, W1 + woff,
                                                 b_h + i * 512,
                                                 fid_h + i * 512,
                                                 m_h + i * 512,
                                                 (uint32_t*)n0, (uint32_t*)n1,
                                                 nullptr, 512, 1);
        uint4* t0 = n0; uint4* t1 = n1;
        n0 = (uint4*)c0; n1 = (uint4*)c1;
        c0 = t0; c1 = t1;
    }

    // output layer: plain fp32 row-major out
    fused_layer16<<<g128, blk, SMEM_BYTES>>>(c0, c1,
                                             W0 + 20 * W_NBLK_U4, W1 + 20 * W_NBLK_U4,
                                             b_out, fid_out, m_out,
                                             nullptr, nullptr, out, 128, 0);
}